// round 10
// baseline (speedup 1.0000x reference)
#include <cuda_runtime.h>

#define Bq   256
#define Tq   1024
#define NUMq 126
#define LBLq 128

__device__ int d_perm[Bq];

// Rank sequences by length (desc). CTA i runs ranks i and 255-i in two
// independent sub-groups, so long+short pairing is placement-independent.
__global__ void rank_kernel(const int* __restrict__ lens) {
    __shared__ int sl[Bq];
    int i = threadIdx.x;
    int li = lens[i];
    sl[i] = li;
    __syncthreads();
    int r = 0;
    #pragma unroll 8
    for (int k = 0; k < Bq; ++k) {
        int lk = sl[k];
        r += (lk > li) || (lk == li && k < i);
    }
    d_perm[r] = i;
}

__device__ __forceinline__ void fma2(unsigned long long& d,
                                     unsigned long long a, unsigned long long b) {
    asm("fma.rn.f32x2 %0, %1, %2, %0;" : "+l"(d) : "l"(a), "l"(b));
}
__device__ __forceinline__ unsigned long long add2(unsigned long long a,
                                                   unsigned long long b) {
    unsigned long long d;
    asm("add.rn.f32x2 %0, %1, %2;" : "=l"(d) : "l"(a), "l"(b));
    return d;
}
__device__ __forceinline__ unsigned long long pack2(float lo, float hi) {
    unsigned long long d;
    asm("mov.b64 %0, {%1, %2};" : "=l"(d) : "f"(lo), "f"(hi));
    return d;
}
__device__ __forceinline__ void unpack2(unsigned long long d, float& lo, float& hi) {
    asm("mov.b64 {%0, %1}, %2;" : "=f"(lo), "=f"(hi) : "l"(d));
}

__global__ __launch_bounds__(256, 1)
void crf_kernel(const float* __restrict__ logits,
                const int*   __restrict__ labels,
                const int*   __restrict__ lens,
                const float* __restrict__ trans,
                float*       __restrict__ out) {
    const int cta = blockIdx.x;            // 0..127
    const int sub = threadIdx.x >> 7;      // sub-group 0 or 1
    const int jt  = threadIdx.x & 127;     // thread id within sub-group
    const int slot = sub ? (Bq - 1 - cta) : cta;
    const int b    = d_perm[slot];
    const int len  = lens[b];

    const int w = jt >> 5;
    const int l = jt & 31;
    const int h = l >> 4;                  // k-half (64 cols each)
    const int g = l & 15;                  // row-group within warp
    const int rowbase = w * 32 + g * 2;    // this thread's 2 output rows
    const int barid = sub + 1;

    __shared__ __align__(128) float abuf[2][2][LBLq];  // [sub][buf][label]
    __shared__ float red[2][4];

    #define SUBBAR() asm volatile("bar.sync %0, 128;" :: "r"(barid) : "memory")

    // ---- expT tile: 2 rows x 64 cols (half h) ----
    unsigned long long R2[2][32];
    #pragma unroll
    for (int r = 0; r < 2; ++r) {
        const float4* trow = (const float4*)(trans + (rowbase + r) * LBLq + h * 64);
        #pragma unroll
        for (int s = 0; s < 16; ++s) {
            float4 v = trow[s];
            R2[r][2 * s]     = pack2(__expf(v.x), __expf(v.y));
            R2[r][2 * s + 1] = pack2(__expf(v.z), __expf(v.w));
        }
    }
    float vmask[2];
    vmask[0] = (rowbase + 0 < NUMq) ? 1.f : 0.f;
    vmask[1] = (rowbase + 1 < NUMq) ? 1.f : 0.f;
    const int rr0 = (rowbase + 0 < NUMq) ? (rowbase + 0) : (NUMq - 1);
    const int rr1 = (rowbase + 1 < NUMq) ? (rowbase + 1) : (NUMq - 1);

    // ---- gold path score (cooperative over t within sub-group) ----
    const int lb = b * Tq;
    const float* lgb = logits + (size_t)lb * NUMq;
    float gacc = 0.f;
    for (int t = jt; t < len; t += 128) {
        int lab = labels[lb + t];
        gacc += lgb[t * NUMq + lab];
        int prev = (t == 0) ? (LBLq - 2) : labels[lb + t - 1];
        gacc += trans[lab * LBLq + prev];
    }
    if (jt == 0) gacc += trans[(LBLq - 1) * LBLq + labels[lb + len - 1]];
    #pragma unroll
    for (int d = 16; d >= 1; d >>= 1)
        gacc += __shfl_xor_sync(0xffffffffu, gacc, d);
    if (l == 0) red[sub][w] = gacc;
    SUBBAR();
    float gold = 0.f;
    if (jt == 0)
        gold = (red[sub][0] + red[sub][1]) + (red[sub][2] + red[sub][3]);

    // ---- init alpha0 = onehot(start=126) ----
    abuf[sub][0][jt] = (jt == (LBLq - 2)) ? 1.0f : 0.0f;

    // ---- logit queues + precomputed exp weights for current group ----
    float cur[4][2], nxt[4][2], we[4][2];
    #pragma unroll
    for (int q = 0; q < 4; ++q) {
        int tt = (q < len) ? q : (len - 1);
        cur[q][0] = lgb[tt * NUMq + rr0];
        cur[q][1] = lgb[tt * NUMq + rr1];
        int t2 = (4 + q < len) ? (4 + q) : (len - 1);
        nxt[q][0] = lgb[t2 * NUMq + rr0];
        nxt[q][1] = lgb[t2 * NUMq + rr1];
    }
    #pragma unroll
    for (int q = 0; q < 4; ++q) {
        we[q][0] = __expf(cur[q][0]) * vmask[0];
        we[q][1] = __expf(cur[q][1]) * vmask[1];
    }

    float logc = 0.f;
    float inv  = 1.0f;
    SUBBAR();

#define STEP(PH, T)                                                             \
    {                                                                           \
        const int rb = (PH) & 1, wb = 1 - rb;                                   \
        if ((PH) == 0 && (T) != 0) {                                            \
            _Pragma("unroll")                                                   \
            for (int q = 0; q < 4; ++q) {                                       \
                cur[q][0] = nxt[q][0];                                          \
                cur[q][1] = nxt[q][1];                                          \
                int tt = ((T) + 4 + q < len) ? ((T) + 4 + q) : (len - 1);       \
                nxt[q][0] = lgb[tt * NUMq + rr0];                               \
                nxt[q][1] = lgb[tt * NUMq + rr1];                               \
            }                                                                   \
            _Pragma("unroll")                                                   \
            for (int q = 0; q < 4; ++q) {                                       \
                we[q][0] = __expf(cur[q][0]) * vmask[0];                        \
                we[q][1] = __expf(cur[q][1]) * vmask[1];                        \
            }                                                                   \
        }                                                                       \
        const ulonglong2* aa = (const ulonglong2*)(abuf[sub][rb] + h * 64);     \
        unsigned long long a00 = 0ull, a01 = 0ull, a02 = 0ull, a03 = 0ull;      \
        unsigned long long a10 = 0ull, a11 = 0ull, a12 = 0ull, a13 = 0ull;      \
        unsigned long long s0 = 0ull, s1 = 0ull, s2 = 0ull, s3 = 0ull;          \
        _Pragma("unroll")                                                       \
        for (int s = 0; s < 16; ++s) {                                          \
            ulonglong2 A = aa[s];                                               \
            if ((PH) == 0) {                                                    \
                if (s & 1) { s2 = add2(s2, A.x); s3 = add2(s3, A.y); }          \
                else       { s0 = add2(s0, A.x); s1 = add2(s1, A.y); }          \
            }                                                                   \
            if (s & 1) {                                                        \
                fma2(a02, R2[0][2 * s], A.x); fma2(a03, R2[0][2 * s + 1], A.y); \
                fma2(a12, R2[1][2 * s], A.x); fma2(a13, R2[1][2 * s + 1], A.y); \
            } else {                                                            \
                fma2(a00, R2[0][2 * s], A.x); fma2(a01, R2[0][2 * s + 1], A.y); \
                fma2(a10, R2[1][2 * s], A.x); fma2(a11, R2[1][2 * s + 1], A.y); \
            }                                                                   \
        }                                                                       \
        if ((PH) == 0) {                                                        \
            float tlo, thi;                                                     \
            unpack2(add2(add2(s0, s1), add2(s2, s3)), tlo, thi);                \
            float ts = tlo + thi;                                               \
            ts += __shfl_xor_sync(0xffffffffu, ts, 16);                         \
            inv   = __fdividef(1.0f, ts);                                       \
            logc += __logf(ts);                                                 \
        }                                                                       \
        float lo, hi, ps0, ps1;                                                 \
        unpack2(add2(add2(a00, a01), add2(a02, a03)), lo, hi); ps0 = lo + hi;   \
        ps0 += __shfl_xor_sync(0xffffffffu, ps0, 16);                           \
        unpack2(add2(add2(a10, a11), add2(a12, a13)), lo, hi); ps1 = lo + hi;   \
        ps1 += __shfl_xor_sync(0xffffffffu, ps1, 16);                           \
        float w0 = we[(PH)][0], w1 = we[(PH)][1];                               \
        if ((PH) == 1) { w0 *= inv; w1 *= inv; }                                \
        if (h == 0)                                                             \
            *(float2*)&abuf[sub][wb][rowbase] = make_float2(w0 * ps0, w1 * ps1);\
        SUBBAR();                                                               \
    }

    int t0 = 0;
    for (; t0 + 4 <= len; t0 += 4) {
        STEP(0, t0)
        STEP(1, t0 + 1)
        STEP(2, t0 + 2)
        STEP(3, t0 + 3)
    }
    const int rem = len - t0;
    if (rem > 0) STEP(0, t0)
    if (rem > 1) STEP(1, t0 + 1)
    if (rem > 2) STEP(2, t0 + 2)
#undef STEP

    // ---- finish: alpha *= exp(trans[end]); fold pending inv if the sequence
    // ended right after a group head (inv computed but never applied).
    const int rbf = len & 1;
    float fv = abuf[sub][rbf][jt] * __expf(trans[(LBLq - 1) * LBLq + jt]);
    if ((len & 3) == 1) fv *= inv;
    #pragma unroll
    for (int d = 16; d >= 1; d >>= 1)
        fv += __shfl_xor_sync(0xffffffffu, fv, d);
    if (l == 0) red[sub][w] = fv;
    SUBBAR();
    if (jt == 0) {
        float fs = (red[sub][0] + red[sub][1]) + (red[sub][2] + red[sub][3]);
        out[b] = gold - (logc + __logf(fs));
    }
    #undef SUBBAR
}

extern "C" void kernel_launch(void* const* d_in, const int* in_sizes, int n_in,
                              void* d_out, int out_size) {
    const float* logits = (const float*)d_in[0];
    const int*   labels = (const int*)d_in[1];
    const int*   lens   = (const int*)d_in[2];
    const float* trans  = (const float*)d_in[3];
    float*       out    = (float*)d_out;

    rank_kernel<<<1, Bq>>>(lens);
    crf_kernel<<<Bq / 2, 256>>>(logits, labels, lens, trans, out);
}